// round 16
// baseline (speedup 1.0000x reference)
#include <cuda_runtime.h>
#include <cuda_fp16.h>
#include <cstdint>

#define T_  4
#define B_  8192
#define D_  1024
#define U_  512
#define UE  4096
#define NTOT 4096

// ---------------------------------------------------------------------------
// Device scratch
// ---------------------------------------------------------------------------
__device__ __half g_xh[(size_t)B_ * D_];           // x in fp16
__device__ __half g_bt0h[5ull * NTOT * D_];        // level-0 B^T (N-major, fp16)
__device__ __half g_bt1h[5ull * NTOT * U_];
__device__ __half g_a1h[5ull * B_ * U_];           // level-1 A (4 tasks + share), fp16
__device__ float g_wt0[104 * D_];                  // level-0 gate weights, transposed [c][k]
__device__ float g_wt1[64 * U_];                   // level-1 gate weights, transposed
__device__ float g_g0[(size_t)T_ * B_ * 16];
__device__ float g_gs[(size_t)B_ * 40];
__device__ float g_g1[(size_t)T_ * B_ * 16];

// ---------------------------------------------------------------------------
// PTX helpers (baseline sm_80+ only)
// ---------------------------------------------------------------------------
__device__ __forceinline__ uint32_t smem_u32(const void* p) {
    uint32_t a;
    asm("{ .reg .u64 t; cvta.to.shared.u64 t, %1; cvt.u32.u64 %0, t; }" : "=r"(a) : "l"(p));
    return a;
}
__device__ __forceinline__ void cp16(uint32_t dst, const void* src) {
    asm volatile("cp.async.cg.shared.global [%0], [%1], 16;" :: "r"(dst), "l"(src));
}
__device__ __forceinline__ void ldsm4(uint32_t* r, uint32_t addr) {
    asm volatile("ldmatrix.sync.aligned.m8n8.x4.shared.b16 {%0,%1,%2,%3}, [%4];"
        : "=r"(r[0]), "=r"(r[1]), "=r"(r[2]), "=r"(r[3]) : "r"(addr));
}
__device__ __forceinline__ void mma16816(float* c, const uint32_t* a, uint32_t b0, uint32_t b1) {
    asm volatile("mma.sync.aligned.m16n8k16.row.col.f32.f16.f16.f32 "
        "{%0,%1,%2,%3}, {%4,%5,%6,%7}, {%8,%9}, {%0,%1,%2,%3};"
        : "+f"(c[0]), "+f"(c[1]), "+f"(c[2]), "+f"(c[3])
        : "r"(a[0]), "r"(a[1]), "r"(a[2]), "r"(a[3]), "r"(b0), "r"(b1));
}
__device__ __forceinline__ float red4(float p) {
    p += __shfl_xor_sync(0xffffffffu, p, 1);
    p += __shfl_xor_sync(0xffffffffu, p, 2);
    return p;
}
__device__ __forceinline__ void store_h4(__half* h, size_t off, float4 v) {
    *(__half2*)&h[off]     = __half2(__float2half_rn(v.x), __float2half_rn(v.y));
    *(__half2*)&h[off + 2] = __half2(__float2half_rn(v.z), __float2half_rn(v.w));
}

// ---------------------------------------------------------------------------
// Conversions (fp32 -> fp16; B transposed to N-major; gate weights transposed)
// ---------------------------------------------------------------------------
__global__ void convX(const float* __restrict__ x, __half* __restrict__ hi) {
    size_t i = (size_t)blockIdx.x * blockDim.x + threadIdx.x;
    float4 v = ((const float4*)x)[i];
    store_h4(hi, 4 * i, v);
}

struct ConvBArgs { const float* src[5]; __half* hi; int K; };

__global__ void convB(ConvBArgs a) {
    __shared__ float s[32][33];
    const int z = blockIdx.z;
    const float* __restrict__ src = a.src[z];
    const int n0 = blockIdx.x * 32, k0 = blockIdx.y * 32;
    const int tx = threadIdx.x, ty = threadIdx.y;
#pragma unroll
    for (int i = 0; i < 4; i++)
        s[ty + i * 8][tx] = src[(size_t)(k0 + ty + i * 8) * UE + n0 + tx];
    __syncthreads();
    __half* oh = a.hi + (size_t)z * NTOT * a.K;
#pragma unroll
    for (int i = 0; i < 4; i++) {
        const int n = n0 + ty + i * 8, k = k0 + tx;
        oh[(size_t)n * a.K + k] = __float2half_rn(s[tx][ty + i * 8]);
    }
}

__global__ void convG0(const float* __restrict__ gw0, const float* __restrict__ gws) {
    const int c = blockIdx.x;   // 0..103
    for (int k = threadIdx.x; k < D_; k += 256) {
        float v = (c < 64) ? gw0[(size_t)(c >> 4) * D_ * 16 + (size_t)k * 16 + (c & 15)]
                           : gws[(size_t)k * 40 + (c - 64)];
        g_wt0[(size_t)c * D_ + k] = v;
    }
}
__global__ void convG1(const float* __restrict__ gw1) {
    const int c = blockIdx.x;   // 0..63
    for (int k = threadIdx.x; k < U_; k += 256)
        g_wt1[(size_t)c * U_ + k] =
            gw1[(size_t)(c >> 4) * U_ * 16 + (size_t)k * 16 + (c & 15)];
}

// ---------------------------------------------------------------------------
// GEMM machinery: 128x128 tile, K-step 32, 3-stage cp.async, 8 warps,
// single-product fp16 (Ah x Bh).
// ---------------------------------------------------------------------------
#define MAT_BYTES 8192
#define STAGE_BYTES (2 * MAT_BYTES)         // 16 KB: Ah, Bh
#define SM_STK  (3 * STAGE_BYTES)           // staging float[128][16]  @48KB
#define SM_SSH  (SM_STK + 8192)             // share accum float[128][16]
#define SM_SES  (SM_SSH + 8192)             // es tile __half[128][128] (32 KB)
#define SMEM_B  (SM_SES + 32768)            // 96 KB total

template<int KK>
__device__ __forceinline__ void kloop(const __half* __restrict__ A_h,
                                      const __half* __restrict__ B_h,
                                      uint32_t sb, int rlo, int ch, int dsw,
                                      const uint32_t (&aoff)[2][2],
                                      const uint32_t (&boff)[4][2],
                                      float (&acc)[2][8][4]) {
    constexpr int nk = KK / 32;
    const __half* srcs[2] = { A_h, B_h };
    auto load_stage = [&](int buf, int kc) {
        const uint32_t base = sb + (uint32_t)buf * STAGE_BYTES;
#pragma unroll
        for (int i = 0; i < 4; i++) {
            const int mat = i >> 1;
            const int r   = ((i & 1) << 6) + rlo;
            cp16(base + mat * MAT_BYTES + r * 64 + dsw,
                 srcs[mat] + (size_t)r * KK + kc + ch * 8);
        }
        asm volatile("cp.async.commit_group;" ::: "memory");
    };
    load_stage(0, 0);
    load_stage(1, 32);
    int cb = 0;
    for (int c = 0; c < nk; c++) {
        if (c + 1 < nk) asm volatile("cp.async.wait_group 1;" ::: "memory");
        else            asm volatile("cp.async.wait_group 0;" ::: "memory");
        __syncthreads();
        if (c + 2 < nk) {
            int nb = cb + 2; if (nb >= 3) nb -= 3;
            load_stage(nb, (c + 2) * 32);
        }
        const uint32_t st = sb + (uint32_t)cb * STAGE_BYTES;
        if (++cb == 3) cb = 0;
#pragma unroll
        for (int ks = 0; ks < 2; ks++) {
            uint32_t ah[2][4];
#pragma unroll
            for (int i = 0; i < 2; i++) ldsm4(ah[i], st + aoff[i][ks]);
            uint32_t bf[4][4];
#pragma unroll
            for (int j = 0; j < 4; j++) ldsm4(bf[j], st + MAT_BYTES + boff[j][ks]);
#pragma unroll
            for (int i = 0; i < 2; i++)
#pragma unroll
                for (int j = 0; j < 4; j++) {
                    mma16816(acc[i][2 * j],     ah[i], bf[j][0], bf[j][2]);
                    mma16816(acc[i][2 * j + 1], ah[i], bf[j][1], bf[j][3]);
                }
        }
    }
}

#define GEOM() \
    const int id = blockIdx.x; \
    const int nt = (id >> 4) & 31; \
    const int mt = (id & 15) + ((id >> 9) << 4); \
    const int n0 = nt << 7, m0 = mt << 7; \
    const int u0 = nt << 4; (void)u0; \
    const int tid = threadIdx.x; \
    const int lane = tid & 31; \
    const int w = tid >> 5, wm = w & 3, wn = w >> 2, hb = lane >> 4; \
    const int rlo = tid >> 2, ch = tid & 3; \
    const int dsw = ((ch ^ ((rlo >> 1) & 3)) << 4); \
    uint32_t aoff[2][2], boff[4][2]; \
    _Pragma("unroll") for (int i = 0; i < 2; i++) { \
        const int rA = 32 * wm + 16 * i + (lane & 15); \
        const int csw = (rA >> 1) & 3; \
        _Pragma("unroll") for (int ks = 0; ks < 2; ks++) \
            aoff[i][ks] = (uint32_t)(rA * 64 + (((2 * ks + hb) ^ csw) << 4)); \
    } \
    _Pragma("unroll") for (int j = 0; j < 4; j++) { \
        const int rB = 64 * wn + 16 * j + (((lane >> 3) & 1) << 3) + (lane & 7); \
        const int csw = (rB >> 1) & 3; \
        _Pragma("unroll") for (int ks = 0; ks < 2; ks++) \
            boff[j][ks] = (uint32_t)(rB * 64 + (((2 * ks + hb) ^ csw) << 4)); \
    }

#define ZERO_ACC() \
    float acc[2][8][4]; \
    _Pragma("unroll") for (int i = 0; i < 2; i++) \
        _Pragma("unroll") for (int j = 0; j < 8; j++) \
            _Pragma("unroll") for (int q = 0; q < 4; q++) acc[i][j][q] = 0.f;

struct FGArgs {
    const __half* Bh[5];     // 4 tasks + share
    const float* bias[5];
};

// ---------------------------------------------------------------------------
// Level-0 fused GEMM: share expert (t=4) -> smem es tile, then tasks t=0..3
// with gate combine; writes a1 fp16 (tasks and share).
// ---------------------------------------------------------------------------
__global__ __launch_bounds__(256, 2) void fgemmB0(FGArgs args) {
    extern __shared__ __align__(128) char smem[];
    const uint32_t sb = smem_u32(smem);
    float* stk = (float*)(smem + SM_STK);
    float* ssh = (float*)(smem + SM_SSH);
    __half* ses = (__half*)(smem + SM_SES);
    GEOM();
    for (int idx = tid; idx < 2048; idx += 256) ssh[idx] = 0.f;

    const __half* Ah = g_xh + (size_t)m0 * D_;
    const int e2 = 2 * (lane & 3);

    // ---- share expert -> es tile in smem (fp16) ----
    {
        ZERO_ACC();
        kloop<D_>(Ah, args.Bh[4] + (size_t)n0 * D_, sb, rlo, ch, dsw, aoff, boff, acc);
        const float* __restrict__ bias = args.bias[4];
#pragma unroll
        for (int i = 0; i < 2; i++) {
            const int r0 = 32 * wm + 16 * i + (lane >> 2), r1 = r0 + 8;
#pragma unroll
            for (int j = 0; j < 8; j++) {
                const int ncl = 64 * wn + 8 * j + e2;
                const float b0v = bias[n0 + ncl], b1v = bias[n0 + ncl + 1];
                *(__half2*)&ses[r0 * 128 + ncl] = __half2(
                    __float2half_rn(fmaxf(acc[i][j][0] + b0v, 0.f)),
                    __float2half_rn(fmaxf(acc[i][j][1] + b1v, 0.f)));
                *(__half2*)&ses[r1 * 128 + ncl] = __half2(
                    __float2half_rn(fmaxf(acc[i][j][2] + b0v, 0.f)),
                    __float2half_rn(fmaxf(acc[i][j][3] + b1v, 0.f)));
            }
        }
        __syncthreads();
    }

    // ---- tasks ----
#pragma unroll 1
    for (int t = 0; t < 4; t++) {
        ZERO_ACC();
        kloop<D_>(Ah, args.Bh[t] + (size_t)n0 * D_, sb, rlo, ch, dsw, aoff, boff, acc);

        const float* __restrict__ bias = args.bias[t];
#pragma unroll
        for (int i = 0; i < 2; i++) {
            const int r0 = 32 * wm + 16 * i + (lane >> 2), r1 = r0 + 8;
            const float2 ga0 = *(const float2*)&g_g0[((size_t)t * B_ + m0 + r0) * 16 + e2];
            const float2 gb0 = *(const float2*)&g_g0[((size_t)t * B_ + m0 + r0) * 16 + 8 + e2];
            const float2 ga1 = *(const float2*)&g_g0[((size_t)t * B_ + m0 + r1) * 16 + e2];
            const float2 gb1 = *(const float2*)&g_g0[((size_t)t * B_ + m0 + r1) * 16 + 8 + e2];
            const float2 gt0 = *(const float2*)&g_gs[(size_t)(m0 + r0) * 40 + t * 8 + e2];
            const float2 gt1 = *(const float2*)&g_gs[(size_t)(m0 + r1) * 40 + t * 8 + e2];
            float2 gq0 = {0.f, 0.f}, gq1 = {0.f, 0.f};
            if (t == 3) {
                gq0 = *(const float2*)&g_gs[(size_t)(m0 + r0) * 40 + 32 + e2];
                gq1 = *(const float2*)&g_gs[(size_t)(m0 + r1) * 40 + 32 + e2];
            }
#pragma unroll
            for (int j = 0; j < 8; j++) {
                const int ncl = 64 * wn + 8 * j + e2;
                const float b0v = bias[n0 + ncl], b1v = bias[n0 + ncl + 1];
                const float v00 = fmaxf(acc[i][j][0] + b0v, 0.f);
                const float v01 = fmaxf(acc[i][j][1] + b1v, 0.f);
                const float v10 = fmaxf(acc[i][j][2] + b0v, 0.f);
                const float v11 = fmaxf(acc[i][j][3] + b1v, 0.f);
                const float2 es0 = __half22float2(*(const __half2*)&ses[r0 * 128 + ncl]);
                const float2 es1 = __half22float2(*(const __half2*)&ses[r1 * 128 + ncl]);
                float pt0 = red4(v00 * ga0.x + v01 * ga0.y + es0.x * gb0.x + es0.y * gb0.y);
                float pt1 = red4(v10 * ga1.x + v11 * ga1.y + es1.x * gb1.x + es1.y * gb1.y);
                float ps0 = v00 * gt0.x + v01 * gt0.y;
                float ps1 = v10 * gt1.x + v11 * gt1.y;
                if (t == 3) {
                    ps0 += es0.x * gq0.x + es0.y * gq0.y;
                    ps1 += es1.x * gq1.x + es1.y * gq1.y;
                }
                ps0 = red4(ps0); ps1 = red4(ps1);
                if ((lane & 3) == 0) {
                    const int u = 8 * wn + j;
                    stk[r0 * 16 + u] = pt0;
                    stk[r1 * 16 + u] = pt1;
                    ssh[r0 * 16 + u] += ps0;
                    ssh[r1 * 16 + u] += ps1;
                }
            }
        }
        __syncthreads();
        for (int idx = tid; idx < 512; idx += 256) {
            const int r = idx >> 2, c4 = idx & 3;
            float4 tv = *(float4*)&stk[r * 16 + 4 * c4];
            store_h4(g_a1h, ((size_t)t * B_ + m0 + r) * U_ + u0 + 4 * c4, tv);
        }
        __syncthreads();
    }

    for (int idx = tid; idx < 512; idx += 256) {
        const int r = idx >> 2, c4 = idx & 3;
        float4 sv = *(float4*)&ssh[r * 16 + 4 * c4];
        store_h4(g_a1h, ((size_t)4 * B_ + m0 + r) * U_ + u0 + 4 * c4, sv);
    }
}

// ---------------------------------------------------------------------------
// Level-1 fused GEMM: share (t=4) -> es tile, then tasks; writes final out.
// ---------------------------------------------------------------------------
__global__ __launch_bounds__(256, 2) void fgemmB1(FGArgs args, float* __restrict__ out) {
    extern __shared__ __align__(128) char smem[];
    const uint32_t sb = smem_u32(smem);
    float* stk = (float*)(smem + SM_STK);
    __half* ses = (__half*)(smem + SM_SES);
    GEOM();
    const int e2 = 2 * (lane & 3);

    // ---- share expert -> es tile ----
    {
        ZERO_ACC();
        kloop<U_>(g_a1h + ((size_t)4 * B_ + m0) * U_, args.Bh[4] + (size_t)n0 * U_,
                  sb, rlo, ch, dsw, aoff, boff, acc);
        const float* __restrict__ bias = args.bias[4];
#pragma unroll
        for (int i = 0; i < 2; i++) {
            const int r0 = 32 * wm + 16 * i + (lane >> 2), r1 = r0 + 8;
#pragma unroll
            for (int j = 0; j < 8; j++) {
                const int ncl = 64 * wn + 8 * j + e2;
                const float b0v = bias[n0 + ncl], b1v = bias[n0 + ncl + 1];
                *(__half2*)&ses[r0 * 128 + ncl] = __half2(
                    __float2half_rn(fmaxf(acc[i][j][0] + b0v, 0.f)),
                    __float2half_rn(fmaxf(acc[i][j][1] + b1v, 0.f)));
                *(__half2*)&ses[r1 * 128 + ncl] = __half2(
                    __float2half_rn(fmaxf(acc[i][j][2] + b0v, 0.f)),
                    __float2half_rn(fmaxf(acc[i][j][3] + b1v, 0.f)));
            }
        }
        __syncthreads();
    }

#pragma unroll 1
    for (int t = 0; t < 4; t++) {
        ZERO_ACC();
        kloop<U_>(g_a1h + ((size_t)t * B_ + m0) * U_, args.Bh[t] + (size_t)n0 * U_,
                  sb, rlo, ch, dsw, aoff, boff, acc);

        const float* __restrict__ bias = args.bias[t];
#pragma unroll
        for (int i = 0; i < 2; i++) {
            const int r0 = 32 * wm + 16 * i + (lane >> 2), r1 = r0 + 8;
            const float2 ga0 = *(const float2*)&g_g1[((size_t)t * B_ + m0 + r0) * 16 + e2];
            const float2 gb0 = *(const float2*)&g_g1[((size_t)t * B_ + m0 + r0) * 16 + 8 + e2];
            const float2 ga1 = *(const float2*)&g_g1[((size_t)t * B_ + m0 + r1) * 16 + e2];
            const float2 gb1 = *(const float2*)&g_g1[((size_t)t * B_ + m0 + r1) * 16 + 8 + e2];
#pragma unroll
            for (int j = 0; j < 8; j++) {
                const int ncl = 64 * wn + 8 * j + e2;
                const float b0v = bias[n0 + ncl], b1v = bias[n0 + ncl + 1];
                const float v00 = fmaxf(acc[i][j][0] + b0v, 0.f);
                const float v01 = fmaxf(acc[i][j][1] + b1v, 0.f);
                const float v10 = fmaxf(acc[i][j][2] + b0v, 0.f);
                const float v11 = fmaxf(acc[i][j][3] + b1v, 0.f);
                const float2 es0 = __half22float2(*(const __half2*)&ses[r0 * 128 + ncl]);
                const float2 es1 = __half22float2(*(const __half2*)&ses[r1 * 128 + ncl]);
                float pt0 = red4(v00 * ga0.x + v01 * ga0.y + es0.x * gb0.x + es0.y * gb0.y);
                float pt1 = red4(v10 * ga1.x + v11 * ga1.y + es1.x * gb1.x + es1.y * gb1.y);
                if ((lane & 3) == 0) {
                    const int u = 8 * wn + j;
                    stk[r0 * 16 + u] = pt0;
                    stk[r1 * 16 + u] = pt1;
                }
            }
        }
        __syncthreads();
        for (int idx = tid; idx < 512; idx += 256) {
            const int r = idx >> 2, c4 = idx & 3;
            float4 tv = *(float4*)&stk[r * 16 + 4 * c4];
            *(float4*)&out[((size_t)t * B_ + m0 + r) * U_ + u0 + 4 * c4] = tv;
        }
        __syncthreads();
    }
}

// ---------------------------------------------------------------------------
// gates0: transposed weights, contiguous float4 weight streams.
// ---------------------------------------------------------------------------
__global__ __launch_bounds__(256) void gates0(const float* __restrict__ x,
                                              const float* __restrict__ gb0,
                                              const float* __restrict__ gbs) {
    const int b0 = blockIdx.x * 16;
    const int tid = threadIdx.x;
    __shared__ float sx[16][128];
    __shared__ float sz[16][104];

    const bool active = tid < 208;
    const int rh = (tid >= 104) ? 1 : 0;
    const int c  = active ? (tid - rh * 104) : 0;
    const float* wrow = g_wt0 + (size_t)c * D_;

    float acc[8];
#pragma unroll
    for (int r = 0; r < 8; r++) acc[r] = 0.f;

    for (int kc = 0; kc < D_ / 128; kc++) {
        __syncthreads();
#pragma unroll
        for (int p = 0; p < 2; p++) {
            const int idx = tid + p * 256;
            const int row = idx >> 5, c4 = idx & 31;
            *(float4*)&sx[row][c4 * 4] =
                *(const float4*)(x + (size_t)(b0 + row) * D_ + kc * 128 + c4 * 4);
        }
        __syncthreads();
        if (active) {
            const float* wp = wrow + kc * 128;
#pragma unroll 8
            for (int k = 0; k < 128; k += 4) {
                const float4 wv = *(const float4*)(wp + k);
#pragma unroll
                for (int r = 0; r < 8; r++) {
                    float4 xv = *(const float4*)&sx[rh * 8 + r][k];
                    acc[r] += xv.x * wv.x + xv.y * wv.y + xv.z * wv.z + xv.w * wv.w;
                }
            }
        }
    }
    if (active) {
        const float bb = (c < 64) ? gb0[c] : gbs[c - 64];
#pragma unroll
        for (int r = 0; r < 8; r++) sz[rh * 8 + r][c] = acc[r] + bb;
    }
    __syncthreads();

    if (tid < 80) {
        const int r = tid & 15, g = tid >> 4;
        const int base = (g < 4) ? g * 16 : 64;
        const int len  = (g < 4) ? 16 : 40;
        float mx = -1e30f;
        for (int i = 0; i < len; i++) mx = fmaxf(mx, sz[r][base + i]);
        float s = 0.f;
        for (int i = 0; i < len; i++) s += expf(sz[r][base + i] - mx);
        const float inv = 1.f / s;
        if (g < 4) {
            float* o = g_g0 + ((size_t)g * B_ + b0 + r) * 16;
            for (int i = 0; i < 16; i++) o[i] = expf(sz[r][base + i] - mx) * inv;
        } else {
            float* o = g_gs + (size_t)(b0 + r) * 40;
            for (int i = 0; i < 40; i++) o[i] = expf(sz[r][base + i] - mx) * inv;
        }
    }
}

// ---------------------------------------------------------------------------
// gates1: transposed weights, fp16 task inputs (g_a1h).
// ---------------------------------------------------------------------------
__global__ __launch_bounds__(256) void gates1(const float* __restrict__ gb1) {
    const int b0 = blockIdx.x * 16;
    const int tid = threadIdx.x;
    __shared__ float s1[4][16][128];
    __shared__ float sz[16][64];

    const bool active = tid < 128;
    const int rh = (tid >> 6) & 1;
    const int c  = tid & 63;
    const int tt = c >> 4;
    const float* wrow = g_wt1 + (size_t)c * U_;

    float acc[8];
#pragma unroll
    for (int r = 0; r < 8; r++) acc[r] = 0.f;

    for (int kc = 0; kc < U_ / 128; kc++) {
        __syncthreads();
#pragma unroll
        for (int p = 0; p < 16; p++) {
            const int idx = tid + p * 256;         // half2 index, 0..4095
            const int tz = idx >> 10;
            const int row = (idx >> 6) & 15;
            const int cc = idx & 63;
            __half2 hv = *(const __half2*)&g_a1h[((size_t)tz * B_ + b0 + row) * U_ + kc * 128 + cc * 2];
            float2 fv = __half22float2(hv);
            s1[tz][row][cc * 2]     = fv.x;
            s1[tz][row][cc * 2 + 1] = fv.y;
        }
        __syncthreads();
        if (active) {
            const float* wp = wrow + kc * 128;
#pragma unroll 8
            for (int k = 0; k < 128; k += 4) {
                const float4 wv = *(const float4*)(wp + k);
#pragma unroll
                for (int r = 0; r < 8; r++) {
                    float4 xv = *(const float4*)&s1[tt][rh * 8 + r][k];
                    acc[r] += xv.x * wv.x + xv.y * wv.y + xv.z * wv.z + xv.w * wv.w;
                }
            }
        }
    }
    if (active) {
        const float bb = gb1[c];
#pragma unroll
        for (int r = 0; r < 8; r++) sz[rh * 8 + r][c] = acc[r] + bb;
    }
    __syncthreads();

    if (tid < 64) {
        const int r = tid & 15, g = tid >> 4;
        float mx = -1e30f;
        for (int i = 0; i < 16; i++) mx = fmaxf(mx, sz[r][g * 16 + i]);
        float s = 0.f;
        for (int i = 0; i < 16; i++) s += expf(sz[r][g * 16 + i] - mx);
        const float inv = 1.f / s;
        float* o = g_g1 + ((size_t)g * B_ + b0 + r) * 16;
        for (int i = 0; i < 16; i++) o[i] = expf(sz[r][g * 16 + i] - mx) * inv;
    }
}

// ---------------------------------------------------------------------------
// Launch
// ---------------------------------------------------------------------------
extern "C" void kernel_launch(void* const* d_in, const int* in_sizes, int n_in,
                              void* d_out, int out_size) {
    (void)in_sizes; (void)n_in; (void)out_size;
    const float* x    = (const float*)d_in[0];
    const float* ews0 = (const float*)d_in[1];
    const float* ebs0 = (const float*)d_in[2];
    const float* ews1 = (const float*)d_in[3];
    const float* ebs1 = (const float*)d_in[4];
    const float* gws  = (const float*)d_in[5];
    const float* gbs  = (const float*)d_in[6];
    const float* ew0  = (const float*)d_in[7];
    const float* eb0  = (const float*)d_in[8];
    const float* gw0  = (const float*)d_in[9];
    const float* gb0  = (const float*)d_in[10];
    const float* ew1  = (const float*)d_in[11];
    const float* eb1  = (const float*)d_in[12];
    const float* gw1  = (const float*)d_in[13];
    const float* gb1  = (const float*)d_in[14];

    cudaFuncSetAttribute(fgemmB0, cudaFuncAttributeMaxDynamicSharedMemorySize, SMEM_B);
    cudaFuncSetAttribute(fgemmB1, cudaFuncAttributeMaxDynamicSharedMemorySize, SMEM_B);

    __half *xh, *bt0h, *bt1h;
    cudaGetSymbolAddress((void**)&xh,   g_xh);
    cudaGetSymbolAddress((void**)&bt0h, g_bt0h);
    cudaGetSymbolAddress((void**)&bt1h, g_bt1h);

    // conversions
    convX<<<(B_ * D_ / 4) / 256, 256>>>(x, xh);
    convG0<<<104, 256>>>(gw0, gws);
    convG1<<<64, 256>>>(gw1);
    ConvBArgs cb0;
    for (int t = 0; t < 4; t++) cb0.src[t] = ew0 + (size_t)t * D_ * UE;
    cb0.src[4] = ews0; cb0.hi = bt0h; cb0.K = D_;
    convB<<<dim3(NTOT / 32, D_ / 32, 5), dim3(32, 8)>>>(cb0);
    ConvBArgs cb1;
    for (int t = 0; t < 4; t++) cb1.src[t] = ew1 + (size_t)t * U_ * UE;
    cb1.src[4] = ews1; cb1.hi = bt1h; cb1.K = U_;
    convB<<<dim3(NTOT / 32, U_ / 32, 5), dim3(32, 8)>>>(cb1);

    // level 0
    gates0<<<B_ / 16, 256>>>(x, gb0, gbs);
    FGArgs a0;
    for (int t = 0; t < 4; t++) {
        a0.Bh[t] = bt0h + (size_t)t * NTOT * D_;
        a0.bias[t] = eb0 + (size_t)t * UE;
    }
    a0.Bh[4] = bt0h + (size_t)4 * NTOT * D_;
    a0.bias[4] = ebs0;
    fgemmB0<<<2048, 256, SMEM_B>>>(a0);

    // level 1
    gates1<<<B_ / 16, 256>>>(gb1);
    FGArgs a1;
    for (int t = 0; t < 4; t++) {
        a1.Bh[t] = bt1h + (size_t)t * NTOT * U_;
        a1.bias[t] = eb1 + (size_t)t * UE;
    }
    a1.Bh[4] = bt1h + (size_t)4 * NTOT * U_;
    a1.bias[4] = ebs1;
    fgemmB1<<<2048, 256, SMEM_B>>>(a1, (float*)d_out);
}